// round 13
// baseline (speedup 1.0000x reference)
#include <cuda_runtime.h>
#include <cstdint>

#define NB   32
#define NA   8400
#define ROWF 85
#define MD   300
#define TOTAL (NB*NA)
#define CONF_T 0.2f
#define NMS_T  0.45f
#define APB   256                       // anchors per score block
#define TILE_BYTES (APB*ROWF*4)         // 87040, multiple of 16

// output layout: concatenated float32, reference return order
#define OF_BOX  0
#define OF_INZ  38400
#define OF_SC   48000
#define OF_CLS  57600
#define OF_CTR  67200
#define OF_KEEP 86400

__device__ unsigned g_keys[TOTAL];
__device__ float4   g_sbox[NB*MD];
__device__ float    g_sarea[NB*MD];
__device__ unsigned g_flags[NB*20];
__device__ unsigned g_mask[NB*MD*10];

__device__ __forceinline__ uint32_t smem_u32(const void* p) {
    uint32_t a;
    asm("{ .reg .u64 t; cvta.to.shared.u64 t, %1; cvt.u32.u64 %0, t; }"
        : "=r"(a) : "l"(p));
    return a;
}

// ---------------------------------------------------------------------------
// Kernel A: 256 anchors/block via ONE 87KB cp.async.bulk; all 256 threads
// compute the tail (stride-85 LDS, conflict-free).
// ---------------------------------------------------------------------------
__global__ void __launch_bounds__(APB) score_kernel(const float* __restrict__ pred)
{
    extern __shared__ __align__(16) float sm[];
    __shared__ __align__(8) unsigned long long mbar;

    const int tid = threadIdx.x;
    const uint32_t mb  = smem_u32(&mbar);
    const uint32_t dst = smem_u32(sm);
    const char* src = (const char*)pred + (size_t)blockIdx.x * TILE_BYTES;

    if (tid == 0)
        asm volatile("mbarrier.init.shared.b64 [%0], 1;" :: "r"(mb) : "memory");
    __syncthreads();
    if (tid == 0) {
        asm volatile("mbarrier.arrive.expect_tx.shared.b64 _, [%0], %1;"
                     :: "r"(mb), "r"((unsigned)TILE_BYTES) : "memory");
        asm volatile("cp.async.bulk.shared::cta.global.mbarrier::complete_tx::bytes"
                     " [%0], [%1], %2, [%3];"
                     :: "r"(dst), "l"(src), "r"((unsigned)TILE_BYTES), "r"(mb)
                     : "memory");
    }
    asm volatile(
        "{\n\t"
        ".reg .pred P;\n\t"
        "WL_%=:\n\t"
        "mbarrier.try_wait.parity.acquire.cta.shared::cta.b64 P, [%0], 0, 0x989680;\n\t"
        "@P bra.uni WD_%=;\n\t"
        "bra.uni WL_%=;\n\t"
        "WD_%=:\n\t"
        "}" :: "r"(mb) : "memory");

    const float* a = sm + tid * ROWF;       // stride 85: conflict-free

    float obj = a[4];
    float m0 = a[5], m1 = a[6], m2 = a[7], m3 = a[8];
#pragma unroll
    for (int k = 9; k < 85; k += 4) {
        m0 = fmaxf(m0, a[k]);   m1 = fmaxf(m1, a[k+1]);
        m2 = fmaxf(m2, a[k+2]); m3 = fmaxf(m3, a[k+3]);
    }
    float conf  = fmaxf(fmaxf(m0, m1), fmaxf(m2, m3));
    float score = __fmul_rn(obj, conf);

    unsigned key = 0u;
    if (score >= CONF_T) key = __float_as_uint(score) | 0x80000000u;
    g_keys[blockIdx.x * APB + tid] = key;
}

// ---------------------------------------------------------------------------
// Kernel B: per-batch select+sort+decode. PDL: init overlaps score tail.
// ---------------------------------------------------------------------------
struct SelSmem {
    unsigned shi[NA];
    unsigned hist[4096];
    unsigned s8[512];
    unsigned sgsuf[33];
    unsigned long long cand[512];
    unsigned sh_bin, sh_acc, ncand;
    unsigned validw[10], inw[10];
};
#define SEL_SMEM_BYTES ((int)sizeof(SelSmem))

__global__ void __launch_bounds__(1024, 1) select_kernel(const float* __restrict__ pred,
                                                         const float* __restrict__ zone,
                                                         float* __restrict__ out)
{
    extern __shared__ char smem_raw[];
    SelSmem& S = *reinterpret_cast<SelSmem*>(smem_raw);

    const int b   = blockIdx.x;
    const int tid = threadIdx.x;

    // data-independent prelude (overlaps upstream under PDL)
    if (tid == 0) { S.sh_bin = 0u; S.sh_acc = 0u; S.ncand = 0u; }
    if (tid < 10) { S.validw[tid] = 0u; S.inw[tid] = 0u; }
    for (int i = tid; i < 4096; i += 1024) S.hist[i] = 0u;
    __syncthreads();

    cudaGridDependencySynchronize();      // g_keys ready

    {
        const unsigned* __restrict__ keys = g_keys + (size_t)b * NA;
        for (int i = tid; i < NA; i += 1024) {
            unsigned hi = keys[i];
            S.shi[i] = hi;
            unsigned d = hi >> 20;
            unsigned am = __activemask();
            unsigned mm = __match_any_sync(am, d);
            if ((tid & 31) == (int)(__ffs(mm) - 1u))
                atomicAdd(&S.hist[d], (unsigned)__popc(mm));
        }
    }
    __syncthreads();

    unsigned thresh24 = 0u;

#pragma unroll
    for (int pass = 0; pass < 2; ++pass) {
        if (tid < 512) {
            unsigned s = 0;
#pragma unroll
            for (int k = 0; k < 8; ++k) s += S.hist[tid * 8 + k];
            S.s8[tid] = s;
        }
        __syncthreads();
        if (tid < 32) {
            unsigned s = 0;
#pragma unroll
            for (int k = 0; k < 16; ++k) s += S.s8[tid * 16 + k];
#pragma unroll
            for (int off = 1; off < 32; off <<= 1) {
                unsigned v = __shfl_down_sync(0xffffffffu, s, off);
                if (tid + off < 32) s += v;
            }
            S.sgsuf[tid] = s;
            if (tid == 0) S.sgsuf[32] = 0u;
        }
        __syncthreads();
        unsigned need = (unsigned)MD - S.sh_acc;
        if (tid < 512) {
            int g = tid >> 4;
            unsigned ws = 0;
            for (int j = tid + 1; j < (g + 1) * 16; ++j) ws += S.s8[j];
            unsigned above = S.sgsuf[g + 1] + ws;
            unsigned here  = above + S.s8[tid];
            if (here >= need && above < need) {
                unsigned cum = above; int sel = 0;
#pragma unroll
                for (int k = 7; k >= 0; --k) {
                    unsigned c = S.hist[tid * 8 + k];
                    if (cum + c >= need) { sel = k; break; }
                    cum += c;
                }
                S.sh_bin = (unsigned)(tid * 8 + sel);
                S.sh_acc += cum;
            }
        }
        __syncthreads();

        if (pass == 0) {
            unsigned p0 = S.sh_bin;
            __syncthreads();
            for (int i = tid; i < 4096; i += 1024) S.hist[i] = 0u;
            __syncthreads();
            for (int i = tid; i < NA; i += 1024) {
                unsigned hi = S.shi[i];
                if ((hi >> 20) == p0) {
                    unsigned d = (hi >> 8) & 0xFFFu;
                    unsigned am = __activemask();
                    unsigned mm = __match_any_sync(am, d);
                    if ((tid & 31) == (int)(__ffs(mm) - 1u))
                        atomicAdd(&S.hist[d], (unsigned)__popc(mm));
                }
            }
            __syncthreads();
            thresh24 = p0 << 12;
        } else {
            thresh24 |= S.sh_bin;
        }
    }

    for (int i = tid; i < NA; i += 1024) {
        unsigned hi = S.shi[i];
        if ((hi >> 8) >= thresh24) {
            unsigned p = atomicAdd(&S.ncand, 1u);
            if (p < 512u)
                S.cand[p] = ((unsigned long long)hi << 32) | (unsigned)(~(unsigned)i);
        }
    }
    __syncthreads();
    {
        unsigned nc = S.ncand; if (nc > 512u) nc = 512u;
        if (tid < 512 && (unsigned)tid >= nc) S.cand[tid] = 0ull;
    }
    __syncthreads();

    unsigned long long v = (tid < 512) ? S.cand[tid] : 0ull;
    for (int size = 2; size <= 512; size <<= 1) {
        for (int stride = size >> 1; stride > 0; stride >>= 1) {
            if (stride >= 32) {
                __syncthreads();
                if (tid < 512) S.cand[tid] = v;
                __syncthreads();
                if (tid < 512) {
                    unsigned long long vp = S.cand[tid ^ stride];
                    bool takeMax = ((tid & stride) == 0) == ((tid & size) == 0);
                    v = takeMax ? (v > vp ? v : vp) : (v < vp ? v : vp);
                }
            } else if (tid < 512) {
                unsigned long long vp = __shfl_xor_sync(0xffffffffu, v, stride);
                bool takeMax = ((tid & stride) == 0) == ((tid & size) == 0);
                v = takeMax ? (v > vp ? v : vp) : (v < vp ? v : vp);
            }
        }
    }

    if (tid < MD) {
        unsigned long long kk = v;
        unsigned aidx = ~((unsigned)kk);
        bool valid = (kk >> 32) != 0ull;
        if (!valid) aidx = 0;
        const float* a = pred + (size_t)(b * NA + aidx) * ROWF;

        float x = a[0], y = a[1], w = a[2], h = a[3], obj = a[4];

        float conf = a[5]; int cls = 0;
#pragma unroll 8
        for (int k = 1; k < 80; ++k) {
            float c = a[5 + k];
            if (c > conf) { conf = c; cls = k; }       // first-max == jnp.argmax
        }

        float hw = __fmul_rn(w, 0.5f), hh = __fmul_rn(h, 0.5f);
        float4 v0 = make_float4(__fadd_rn(x,-hw), __fadd_rn(y,-hh),
                                __fadd_rn(x, hw), __fadd_rn(y, hh));

        g_sbox[b*MD + tid]  = v0;
        g_sarea[b*MD + tid] = __fmul_rn(fmaxf(__fadd_rn(v0.z, -v0.x), 0.f),
                                        fmaxf(__fadd_rn(v0.w, -v0.y), 0.f));
        if (valid) atomicOr(&S.validw[tid >> 5], 1u << (tid & 31));

        float cx = __fmul_rn(__fadd_rn(v0.x, v0.z), 0.5f);
        float cy = __fmul_rn(__fadd_rn(v0.y, v0.w), 0.5f);

        int cnt = 0;
#pragma unroll
        for (int k2 = 0; k2 < 8; ++k2) {
            int km = (k2 + 7) & 7;
            float xi = zone[2*k2], yi = zone[2*k2+1];
            float xj = zone[2*km], yj = zone[2*km+1];
            bool gyi = yi > cy, gyj = yj > cy;
            if (gyi != gyj) {
                float gx = __fadd_rn(
                    __fdiv_rn(__fmul_rn(__fadd_rn(xj,-xi), __fadd_rn(cy,-yi)),
                              __fadd_rn(yj,-yi)), xi);
                if (gx > cx) cnt++;
            }
        }
        if (cnt & 1) atomicOr(&S.inw[tid >> 5], 1u << (tid & 31));

        size_t o = (size_t)b * MD + tid;
        out[OF_BOX + o*4 + 0] = v0.y;  out[OF_BOX + o*4 + 1] = v0.x;
        out[OF_BOX + o*4 + 2] = v0.w;  out[OF_BOX + o*4 + 3] = v0.z;
        out[OF_SC  + o]       = fmaxf(obj, conf);
        out[OF_CLS + o]       = (float)cls;
        out[OF_CTR + o*2]     = cy;    out[OF_CTR + o*2 + 1] = cx;
    }
    __syncthreads();
    if (tid < 10) {
        g_flags[b*20 + tid]      = S.validw[tid];
        g_flags[b*20 + 10 + tid] = S.inw[tid];
    }
}

// ---------------------------------------------------------------------------
// Kernel C: suppression bitmask (320 blocks x 640). PDL-gated.
// ---------------------------------------------------------------------------
__global__ void __launch_bounds__(640) mask_kernel()
{
    __shared__ float4 sbb[MD];
    __shared__ float  sA[MD];

    const int b  = blockIdx.x / 10;
    const int rg = blockIdx.x % 10;
    const int tid = threadIdx.x;

    cudaGridDependencySynchronize();      // g_sbox/g_sarea ready

    if (tid < MD) { sbb[tid] = g_sbox[b*MD + tid]; sA[tid] = g_sarea[b*MD + tid]; }
    __syncthreads();

    int w = tid >> 5, l = tid & 31;
    int c    = w % 10;
    int half = w / 10;
    int i0   = rg * 30 + half * 15;
    int j    = c * 32 + l;
    int jmax = c * 32 + 31;
    bool jv  = (j < MD);
    float4 bj = jv ? sbb[j] : make_float4(0,0,0,0);
    float  ja = jv ? sA[j] : 0.f;

    for (int i = i0; i < i0 + 15; ++i) {
        unsigned bits = 0u;
        if (jmax > i) {
            float4 bi = sbb[i];
            float  ia = sA[i];
            bool sup = false;
            if (jv && j > i) {
                float ltx = fmaxf(bi.x, bj.x), lty = fmaxf(bi.y, bj.y);
                float rbx = fminf(bi.z, bj.z), rby = fminf(bi.w, bj.w);
                float iw  = fmaxf(__fadd_rn(rbx, -ltx), 0.f);
                float ih  = fmaxf(__fadd_rn(rby, -lty), 0.f);
                float inter = __fmul_rn(iw, ih);
                float denom = __fadd_rn(__fadd_rn(__fadd_rn(ia, ja), -inter), 1e-9f);
                sup = inter > __fmul_rn(NMS_T, denom);
            }
            bits = __ballot_sync(0xffffffffu, sup);
        }
        if (l == 0) g_mask[(b*MD + i)*10 + c] = bits;
    }
}

// ---------------------------------------------------------------------------
// Kernel D: branchless block-closure greedy scan (R8 version). PDL-gated.
// ---------------------------------------------------------------------------
__global__ void __launch_bounds__(512, 1) fin_kernel(float* __restrict__ out)
{
    __shared__ unsigned smask[320*10];
    __shared__ unsigned keepw[10];
    __shared__ unsigned flg[20];

    const int b   = blockIdx.x;
    const int tid = threadIdx.x;

    for (int i = 3000 + tid; i < 3200; i += 512) smask[i] = 0u;   // prelude

    cudaGridDependencySynchronize();      // g_mask ready

    {
        const uint4* src = reinterpret_cast<const uint4*>(g_mask + b*MD*10);
        uint4* dst = reinterpret_cast<uint4*>(smask);
        for (int i = tid; i < 750; i += 512) dst[i] = src[i];
    }
    if (tid < 20) flg[tid] = g_flags[b*20 + tid];
    __syncthreads();

    if (tid < 32) {
        const int l  = tid;
        const int lw = (l < 10) ? l : 0;
        unsigned kw = (l < 10) ? flg[l] : 0u;

        for (int blk = 0; blk < 10; ++blk) {
            unsigned alive = __shfl_sync(0xffffffffu, kw, blk);
            const int base = blk * 32;

            unsigned r[32];
#pragma unroll
            for (int k = 0; k < 32; ++k)
                r[k] = smask[(base + k)*10 + blk];

#pragma unroll
            for (int k = 0; k < 32; ++k)
                alive &= ~(r[k] & (unsigned)(((int)(alive << (31 - k))) >> 31));

#pragma unroll
            for (int k = 0; k < 32; ++k) {
                unsigned am = (unsigned)(((int)(alive << (31 - k))) >> 31);
                kw &= ~(smask[(base + k)*10 + lw] & am);
            }
        }
        if (l < 10) keepw[l] = kw;
    }
    __syncthreads();

    if (tid < MD) {
        unsigned kp = (keepw[tid >> 5] >> (tid & 31)) & 1u;
        unsigned in = (flg[10 + (tid >> 5)] >> (tid & 31)) & 1u;
        size_t o = (size_t)b * MD + tid;
        out[OF_KEEP + o] = (float)kp;
        out[OF_INZ  + o] = (kp && in) ? 1.f : 0.f;
    }
}

// ---------------------------------------------------------------------------
static void launch_pdl(const void* func, dim3 grid, dim3 block, size_t smem,
                       void** args)
{
    cudaLaunchConfig_t cfg = {};
    cfg.gridDim = grid;  cfg.blockDim = block;
    cfg.dynamicSmemBytes = smem;  cfg.stream = 0;
    cudaLaunchAttribute at[1];
    at[0].id = cudaLaunchAttributeProgrammaticStreamSerialization;
    at[0].val.programmaticStreamSerializationAllowed = 1;
    cfg.attrs = at;  cfg.numAttrs = 1;
    cudaLaunchKernelExC(&cfg, func, args);
}

extern "C" void kernel_launch(void* const* d_in, const int* in_sizes, int n_in,
                              void* d_out, int out_size)
{
    const float* pred = (const float*)d_in[0];
    const float* zone = (const float*)d_in[1];
    float* out = (float*)d_out;

    static int attr_done = 0;
    if (!attr_done) {
        cudaFuncSetAttribute(score_kernel,
                             cudaFuncAttributeMaxDynamicSharedMemorySize,
                             TILE_BYTES);
        cudaFuncSetAttribute(select_kernel,
                             cudaFuncAttributeMaxDynamicSharedMemorySize,
                             SEL_SMEM_BYTES);
        attr_done = 1;
    }

    score_kernel<<<TOTAL / APB, APB, TILE_BYTES>>>(pred);

    {
        void* a1[3] = { (void*)&pred, (void*)&zone, (void*)&out };
        launch_pdl((const void*)select_kernel, dim3(NB), dim3(1024),
                   SEL_SMEM_BYTES, a1);
        launch_pdl((const void*)mask_kernel, dim3(NB * 10), dim3(640), 0, nullptr);
        void* a3[1] = { (void*)&out };
        launch_pdl((const void*)fin_kernel, dim3(NB), dim3(512), 0, a3);
    }
}

// round 14
// speedup vs baseline: 1.0122x; 1.0122x over previous
#include <cuda_runtime.h>
#include <cstdint>

#define NB   32
#define NA   8400
#define ROWF 85
#define MD   300
#define TOTAL (NB*NA)
#define CONF_T 0.2f
#define NMS_T  0.45f
#define TILE_BYTES (128*ROWF*4)   // 43520

// output layout: concatenated float32, reference return order
#define OF_BOX  0
#define OF_INZ  38400
#define OF_SC   48000
#define OF_CLS  57600
#define OF_CTR  67200
#define OF_KEEP 86400

__device__ unsigned g_keys[TOTAL];
__device__ float4   g_sbox[NB*MD];
__device__ float    g_sarea[NB*MD];
__device__ unsigned g_flags[NB*20];
__device__ unsigned g_mask[NB*MD*10];

__device__ __forceinline__ uint32_t smem_u32(const void* p) {
    uint32_t a;
    asm("{ .reg .u64 t; cvta.to.shared.u64 t, %1; cvt.u32.u64 %0, t; }"
        : "=r"(a) : "l"(p));
    return a;
}
__device__ __forceinline__ void tma_1d(uint32_t dst, const void* src,
                                       unsigned bytes, uint32_t mb) {
    asm volatile("cp.async.bulk.shared::cta.global.mbarrier::complete_tx::bytes"
                 " [%0], [%1], %2, [%3];"
                 :: "r"(dst), "l"(src), "r"(bytes), "r"(mb) : "memory");
}
__device__ __forceinline__ void mbar_init1(uint32_t mb) {
    asm volatile("mbarrier.init.shared.b64 [%0], 1;" :: "r"(mb) : "memory");
}
__device__ __forceinline__ void mbar_expect(uint32_t mb, unsigned bytes) {
    asm volatile("mbarrier.arrive.expect_tx.shared.b64 _, [%0], %1;"
                 :: "r"(mb), "r"(bytes) : "memory");
}
__device__ __forceinline__ void mbar_wait0(uint32_t mb) {
    asm volatile(
        "{\n\t"
        ".reg .pred P;\n\t"
        "WL_%=:\n\t"
        "mbarrier.try_wait.parity.acquire.cta.shared::cta.b64 P, [%0], 0, 0x989680;\n\t"
        "@P bra.uni WD_%=;\n\t"
        "bra.uni WL_%=;\n\t"
        "WD_%=:\n\t"
        "}" :: "r"(mb) : "memory");
}

// ---------------------------------------------------------------------------
// Kernel A (R12): 128 anchors/block, one 43.5KB TMA copy, 128-thread tail.
// ---------------------------------------------------------------------------
__global__ void __launch_bounds__(256) score_kernel(const float* __restrict__ pred)
{
    __shared__ __align__(16) float sm[128 * ROWF];
    __shared__ __align__(8)  unsigned long long mbar;

    const int tid = threadIdx.x;
    const uint32_t mb  = smem_u32(&mbar);
    const uint32_t dst = smem_u32(sm);
    const char* src = (const char*)pred + (size_t)blockIdx.x * TILE_BYTES;

    if (tid == 0) mbar_init1(mb);
    __syncthreads();
    if (tid == 0) {
        mbar_expect(mb, (unsigned)TILE_BYTES);
        tma_1d(dst, src, (unsigned)TILE_BYTES, mb);
    }
    mbar_wait0(mb);

    if (tid < 128) {
        const float* a = sm + tid * ROWF;     // stride 85: conflict-free

        float obj = a[4];
        float m0 = a[5], m1 = a[6], m2 = a[7], m3 = a[8];
#pragma unroll
        for (int k = 9; k < 85; k += 4) {
            m0 = fmaxf(m0, a[k]);   m1 = fmaxf(m1, a[k+1]);
            m2 = fmaxf(m2, a[k+2]); m3 = fmaxf(m3, a[k+3]);
        }
        float conf  = fmaxf(fmaxf(m0, m1), fmaxf(m2, m3));
        float score = __fmul_rn(obj, conf);

        unsigned key = 0u;
        if (score >= CONF_T) key = __float_as_uint(score) | 0x80000000u;
        g_keys[blockIdx.x * 128 + tid] = key;
    }
}

// ---------------------------------------------------------------------------
// Kernel B: per-batch select+sort+decode. Keys staged via TMA (33.6KB);
// hist zeroing overlaps the TMA flight.
// ---------------------------------------------------------------------------
struct SelSmem {
    unsigned shi[NA];                 // 33600 B, 16-aligned target
    unsigned hist[4096];
    unsigned s8[512];
    unsigned sgsuf[33];
    unsigned long long cand[512];
    unsigned long long mbar;
    unsigned sh_bin, sh_acc, ncand;
    unsigned validw[10], inw[10];
};
#define SEL_SMEM_BYTES ((int)sizeof(SelSmem))

__global__ void __launch_bounds__(1024, 1) select_kernel(const float* __restrict__ pred,
                                                         const float* __restrict__ zone,
                                                         float* __restrict__ out)
{
    extern __shared__ __align__(16) char smem_raw[];
    SelSmem& S = *reinterpret_cast<SelSmem*>(smem_raw);

    const int b   = blockIdx.x;
    const int tid = threadIdx.x;
    const uint32_t mb = smem_u32(&S.mbar);

    if (tid == 0) mbar_init1(mb);
    __syncthreads();
    if (tid == 0) {
        mbar_expect(mb, (unsigned)(NA * 4));
        tma_1d(smem_u32(S.shi), g_keys + (size_t)b * NA, (unsigned)(NA * 4), mb);
        S.sh_bin = 0u; S.sh_acc = 0u; S.ncand = 0u;
    }
    if (tid < 10) { S.validw[tid] = 0u; S.inw[tid] = 0u; }
    for (int i = tid; i < 4096; i += 1024) S.hist[i] = 0u;   // overlaps TMA
    __syncthreads();
    mbar_wait0(mb);

    // ---- pass-0 (top 12 bits) histogram from smem ----
    for (int i = tid; i < NA; i += 1024) {
        unsigned d = S.shi[i] >> 20;
        unsigned am = __activemask();
        unsigned mm = __match_any_sync(am, d);
        if ((tid & 31) == (int)(__ffs(mm) - 1u))
            atomicAdd(&S.hist[d], (unsigned)__popc(mm));
    }
    __syncthreads();

    unsigned thresh24 = 0u;

#pragma unroll
    for (int pass = 0; pass < 2; ++pass) {
        if (tid < 512) {
            unsigned s = 0;
#pragma unroll
            for (int k = 0; k < 8; ++k) s += S.hist[tid * 8 + k];
            S.s8[tid] = s;
        }
        __syncthreads();
        if (tid < 32) {
            unsigned s = 0;
#pragma unroll
            for (int k = 0; k < 16; ++k) s += S.s8[tid * 16 + k];
#pragma unroll
            for (int off = 1; off < 32; off <<= 1) {
                unsigned v = __shfl_down_sync(0xffffffffu, s, off);
                if (tid + off < 32) s += v;
            }
            S.sgsuf[tid] = s;
            if (tid == 0) S.sgsuf[32] = 0u;
        }
        __syncthreads();
        unsigned need = (unsigned)MD - S.sh_acc;
        if (tid < 512) {
            int g = tid >> 4;
            unsigned ws = 0;
            for (int j = tid + 1; j < (g + 1) * 16; ++j) ws += S.s8[j];
            unsigned above = S.sgsuf[g + 1] + ws;
            unsigned here  = above + S.s8[tid];
            if (here >= need && above < need) {
                unsigned cum = above; int sel = 0;
#pragma unroll
                for (int k = 7; k >= 0; --k) {
                    unsigned c = S.hist[tid * 8 + k];
                    if (cum + c >= need) { sel = k; break; }
                    cum += c;
                }
                S.sh_bin = (unsigned)(tid * 8 + sel);
                S.sh_acc += cum;
            }
        }
        __syncthreads();

        if (pass == 0) {
            unsigned p0 = S.sh_bin;
            __syncthreads();
            for (int i = tid; i < 4096; i += 1024) S.hist[i] = 0u;
            __syncthreads();
            for (int i = tid; i < NA; i += 1024) {
                unsigned hi = S.shi[i];
                if ((hi >> 20) == p0) {
                    unsigned d = (hi >> 8) & 0xFFFu;
                    unsigned am = __activemask();
                    unsigned mm = __match_any_sync(am, d);
                    if ((tid & 31) == (int)(__ffs(mm) - 1u))
                        atomicAdd(&S.hist[d], (unsigned)__popc(mm));
                }
            }
            __syncthreads();
            thresh24 = p0 << 12;
        } else {
            thresh24 |= S.sh_bin;
        }
    }

    for (int i = tid; i < NA; i += 1024) {
        unsigned hi = S.shi[i];
        if ((hi >> 8) >= thresh24) {
            unsigned p = atomicAdd(&S.ncand, 1u);
            if (p < 512u)
                S.cand[p] = ((unsigned long long)hi << 32) | (unsigned)(~(unsigned)i);
        }
    }
    __syncthreads();
    {
        unsigned nc = S.ncand; if (nc > 512u) nc = 512u;
        if (tid < 512 && (unsigned)tid >= nc) S.cand[tid] = 0ull;
    }
    __syncthreads();

    unsigned long long v = (tid < 512) ? S.cand[tid] : 0ull;
    for (int size = 2; size <= 512; size <<= 1) {
        for (int stride = size >> 1; stride > 0; stride >>= 1) {
            if (stride >= 32) {
                __syncthreads();
                if (tid < 512) S.cand[tid] = v;
                __syncthreads();
                if (tid < 512) {
                    unsigned long long vp = S.cand[tid ^ stride];
                    bool takeMax = ((tid & stride) == 0) == ((tid & size) == 0);
                    v = takeMax ? (v > vp ? v : vp) : (v < vp ? v : vp);
                }
            } else if (tid < 512) {
                unsigned long long vp = __shfl_xor_sync(0xffffffffu, v, stride);
                bool takeMax = ((tid & stride) == 0) == ((tid & size) == 0);
                v = takeMax ? (v > vp ? v : vp) : (v < vp ? v : vp);
            }
        }
    }

    if (tid < MD) {
        unsigned long long kk = v;
        unsigned aidx = ~((unsigned)kk);
        bool valid = (kk >> 32) != 0ull;
        if (!valid) aidx = 0;
        const float* a = pred + (size_t)(b * NA + aidx) * ROWF;

        float x = a[0], y = a[1], w = a[2], h = a[3], obj = a[4];

        float conf = a[5]; int cls = 0;
#pragma unroll 8
        for (int k = 1; k < 80; ++k) {
            float c = a[5 + k];
            if (c > conf) { conf = c; cls = k; }       // first-max == jnp.argmax
        }

        float hw = __fmul_rn(w, 0.5f), hh = __fmul_rn(h, 0.5f);
        float4 v0 = make_float4(__fadd_rn(x,-hw), __fadd_rn(y,-hh),
                                __fadd_rn(x, hw), __fadd_rn(y, hh));

        g_sbox[b*MD + tid]  = v0;
        g_sarea[b*MD + tid] = __fmul_rn(fmaxf(__fadd_rn(v0.z, -v0.x), 0.f),
                                        fmaxf(__fadd_rn(v0.w, -v0.y), 0.f));
        if (valid) atomicOr(&S.validw[tid >> 5], 1u << (tid & 31));

        float cx = __fmul_rn(__fadd_rn(v0.x, v0.z), 0.5f);
        float cy = __fmul_rn(__fadd_rn(v0.y, v0.w), 0.5f);

        int cnt = 0;
#pragma unroll
        for (int k2 = 0; k2 < 8; ++k2) {
            int km = (k2 + 7) & 7;
            float xi = zone[2*k2], yi = zone[2*k2+1];
            float xj = zone[2*km], yj = zone[2*km+1];
            bool gyi = yi > cy, gyj = yj > cy;
            if (gyi != gyj) {
                float gx = __fadd_rn(
                    __fdiv_rn(__fmul_rn(__fadd_rn(xj,-xi), __fadd_rn(cy,-yi)),
                              __fadd_rn(yj,-yi)), xi);
                if (gx > cx) cnt++;
            }
        }
        if (cnt & 1) atomicOr(&S.inw[tid >> 5], 1u << (tid & 31));

        size_t o = (size_t)b * MD + tid;
        out[OF_BOX + o*4 + 0] = v0.y;  out[OF_BOX + o*4 + 1] = v0.x;
        out[OF_BOX + o*4 + 2] = v0.w;  out[OF_BOX + o*4 + 3] = v0.z;
        out[OF_SC  + o]       = fmaxf(obj, conf);
        out[OF_CLS + o]       = (float)cls;
        out[OF_CTR + o*2]     = cy;    out[OF_CTR + o*2 + 1] = cx;
    }
    __syncthreads();
    if (tid < 10) {
        g_flags[b*20 + tid]      = S.validw[tid];
        g_flags[b*20 + 10 + tid] = S.inw[tid];
    }
}

// ---------------------------------------------------------------------------
// Kernel C (R12): suppression bitmask on the full chip (320 blocks x 640).
// ---------------------------------------------------------------------------
__global__ void __launch_bounds__(640) mask_kernel()
{
    __shared__ float4 sbb[MD];
    __shared__ float  sA[MD];

    const int b  = blockIdx.x / 10;
    const int rg = blockIdx.x % 10;
    const int tid = threadIdx.x;

    if (tid < MD) { sbb[tid] = g_sbox[b*MD + tid]; sA[tid] = g_sarea[b*MD + tid]; }
    __syncthreads();

    int w = tid >> 5, l = tid & 31;
    int c    = w % 10;
    int half = w / 10;
    int i0   = rg * 30 + half * 15;
    int j    = c * 32 + l;
    int jmax = c * 32 + 31;
    bool jv  = (j < MD);
    float4 bj = jv ? sbb[j] : make_float4(0,0,0,0);
    float  ja = jv ? sA[j] : 0.f;

    for (int i = i0; i < i0 + 15; ++i) {
        unsigned bits = 0u;
        if (jmax > i) {
            float4 bi = sbb[i];
            float  ia = sA[i];
            bool sup = false;
            if (jv && j > i) {
                float ltx = fmaxf(bi.x, bj.x), lty = fmaxf(bi.y, bj.y);
                float rbx = fminf(bi.z, bj.z), rby = fminf(bi.w, bj.w);
                float iw  = fmaxf(__fadd_rn(rbx, -ltx), 0.f);
                float ih  = fmaxf(__fadd_rn(rby, -lty), 0.f);
                float inter = __fmul_rn(iw, ih);
                float denom = __fadd_rn(__fadd_rn(__fadd_rn(ia, ja), -inter), 1e-9f);
                sup = inter > __fmul_rn(NMS_T, denom);
            }
            bits = __ballot_sync(0xffffffffu, sup);
        }
        if (l == 0) g_mask[(b*MD + i)*10 + c] = bits;
    }
}

// ---------------------------------------------------------------------------
// Kernel D: block-closure greedy scan; mask staged via ONE 12KB TMA copy.
// ---------------------------------------------------------------------------
__global__ void __launch_bounds__(512, 1) fin_kernel(float* __restrict__ out)
{
    __shared__ __align__(16) unsigned smask[320*10];   // rows 300..319 zero
    __shared__ __align__(8)  unsigned long long mbar;
    __shared__ unsigned keepw[10];
    __shared__ unsigned flg[20];

    const int b   = blockIdx.x;
    const int tid = threadIdx.x;
    const uint32_t mb = smem_u32(&mbar);

    if (tid == 0) mbar_init1(mb);
    __syncthreads();
    if (tid == 0) {
        mbar_expect(mb, (unsigned)(MD*10*4));
        tma_1d(smem_u32(smask), g_mask + (size_t)b*MD*10, (unsigned)(MD*10*4), mb);
    }
    for (int i = 3000 + tid; i < 3200; i += 512) smask[i] = 0u;  // overlaps TMA
    if (tid < 20) flg[tid] = g_flags[b*20 + tid];
    __syncthreads();
    mbar_wait0(mb);

    if (tid < 32) {
        const int l  = tid;
        const int lw = (l < 10) ? l : 0;
        unsigned kw = (l < 10) ? flg[l] : 0u;

        for (int blk = 0; blk < 10; ++blk) {
            unsigned alive = __shfl_sync(0xffffffffu, kw, blk);
            const int base = blk * 32;

            unsigned r[32];
#pragma unroll
            for (int k = 0; k < 32; ++k)
                r[k] = smask[(base + k)*10 + blk];     // broadcast LDS

#pragma unroll
            for (int k = 0; k < 32; ++k)
                alive &= ~(r[k] & (unsigned)(((int)(alive << (31 - k))) >> 31));

#pragma unroll
            for (int k = 0; k < 32; ++k) {
                unsigned am = (unsigned)(((int)(alive << (31 - k))) >> 31);
                kw &= ~(smask[(base + k)*10 + lw] & am);
            }
        }
        if (l < 10) keepw[l] = kw;
    }
    __syncthreads();

    if (tid < MD) {
        unsigned kp = (keepw[tid >> 5] >> (tid & 31)) & 1u;
        unsigned in = (flg[10 + (tid >> 5)] >> (tid & 31)) & 1u;
        size_t o = (size_t)b * MD + tid;
        out[OF_KEEP + o] = (float)kp;
        out[OF_INZ  + o] = (kp && in) ? 1.f : 0.f;
    }
}

extern "C" void kernel_launch(void* const* d_in, const int* in_sizes, int n_in,
                              void* d_out, int out_size)
{
    const float* pred = (const float*)d_in[0];
    const float* zone = (const float*)d_in[1];
    float* out = (float*)d_out;

    static int attr_done = 0;
    if (!attr_done) {
        cudaFuncSetAttribute(select_kernel,
                             cudaFuncAttributeMaxDynamicSharedMemorySize,
                             SEL_SMEM_BYTES);
        attr_done = 1;
    }

    score_kernel<<<TOTAL / 128, 256>>>(pred);
    select_kernel<<<NB, 1024, SEL_SMEM_BYTES>>>(pred, zone, out);
    mask_kernel<<<NB * 10, 640>>>();
    fin_kernel<<<NB, 512>>>(out);
}

// round 15
// speedup vs baseline: 1.0405x; 1.0280x over previous
#include <cuda_runtime.h>
#include <cstdint>

#define NB   32
#define NA   8400
#define ROWF 85
#define MD   300
#define TOTAL (NB*NA)
#define CONF_T 0.2f
#define NMS_T  0.45f
#define TILE_BYTES (128*ROWF*4)   // 43520

// output layout: concatenated float32, reference return order
#define OF_BOX  0
#define OF_INZ  38400
#define OF_SC   48000
#define OF_CLS  57600
#define OF_CTR  67200
#define OF_KEEP 86400

__device__ unsigned g_keys[TOTAL];
__device__ float4   g_sbox[NB*MD];
__device__ float    g_sarea[NB*MD];
__device__ unsigned g_flags[NB*20];
__device__ unsigned g_mask[NB*MD*10];

__device__ __forceinline__ uint32_t smem_u32(const void* p) {
    uint32_t a;
    asm("{ .reg .u64 t; cvta.to.shared.u64 t, %1; cvt.u32.u64 %0, t; }"
        : "=r"(a) : "l"(p));
    return a;
}
__device__ __forceinline__ void tma_1d(uint32_t dst, const void* src,
                                       unsigned bytes, uint32_t mb) {
    asm volatile("cp.async.bulk.shared::cta.global.mbarrier::complete_tx::bytes"
                 " [%0], [%1], %2, [%3];"
                 :: "r"(dst), "l"(src), "r"(bytes), "r"(mb) : "memory");
}
__device__ __forceinline__ void mbar_init1(uint32_t mb) {
    asm volatile("mbarrier.init.shared.b64 [%0], 1;" :: "r"(mb) : "memory");
}
__device__ __forceinline__ void mbar_expect(uint32_t mb, unsigned bytes) {
    asm volatile("mbarrier.arrive.expect_tx.shared.b64 _, [%0], %1;"
                 :: "r"(mb), "r"(bytes) : "memory");
}
__device__ __forceinline__ void mbar_wait0(uint32_t mb) {
    asm volatile(
        "{\n\t"
        ".reg .pred P;\n\t"
        "WL_%=:\n\t"
        "mbarrier.try_wait.parity.acquire.cta.shared::cta.b64 P, [%0], 0, 0x989680;\n\t"
        "@P bra.uni WD_%=;\n\t"
        "bra.uni WL_%=;\n\t"
        "WD_%=:\n\t"
        "}" :: "r"(mb) : "memory");
}

// ---------------------------------------------------------------------------
// Kernel A (R12 best): 128 anchors/block, one 43.5KB TMA copy, 128-thr tail.
// ---------------------------------------------------------------------------
__global__ void __launch_bounds__(256) score_kernel(const float* __restrict__ pred)
{
    __shared__ __align__(16) float sm[128 * ROWF];
    __shared__ __align__(8)  unsigned long long mbar;

    const int tid = threadIdx.x;
    const uint32_t mb  = smem_u32(&mbar);
    const uint32_t dst = smem_u32(sm);
    const char* src = (const char*)pred + (size_t)blockIdx.x * TILE_BYTES;

    if (tid == 0) mbar_init1(mb);
    __syncthreads();
    if (tid == 0) {
        mbar_expect(mb, (unsigned)TILE_BYTES);
        tma_1d(dst, src, (unsigned)TILE_BYTES, mb);
    }
    mbar_wait0(mb);

    if (tid < 128) {
        const float* a = sm + tid * ROWF;     // stride 85: conflict-free

        float obj = a[4];
        float m0 = a[5], m1 = a[6], m2 = a[7], m3 = a[8];
#pragma unroll
        for (int k = 9; k < 85; k += 4) {
            m0 = fmaxf(m0, a[k]);   m1 = fmaxf(m1, a[k+1]);
            m2 = fmaxf(m2, a[k+2]); m3 = fmaxf(m3, a[k+3]);
        }
        float conf  = fmaxf(fmaxf(m0, m1), fmaxf(m2, m3));
        float score = __fmul_rn(obj, conf);

        unsigned key = 0u;
        if (score >= CONF_T) key = __float_as_uint(score) | 0x80000000u;
        g_keys[blockIdx.x * 128 + tid] = key;
    }
}

// ---------------------------------------------------------------------------
// Kernel B (R12 best): per-batch select+sort+decode. Fused LDG staging +
// pass-0 histogram (latency hidden by hist compute across 32 warps).
// ---------------------------------------------------------------------------
struct SelSmem {
    unsigned shi[NA];
    unsigned hist[4096];
    unsigned s8[512];
    unsigned sgsuf[33];
    unsigned long long cand[512];
    unsigned sh_bin, sh_acc, ncand;
    unsigned validw[10], inw[10];
};
#define SEL_SMEM_BYTES ((int)sizeof(SelSmem))

__global__ void __launch_bounds__(1024, 1) select_kernel(const float* __restrict__ pred,
                                                         const float* __restrict__ zone,
                                                         float* __restrict__ out)
{
    extern __shared__ char smem_raw[];
    SelSmem& S = *reinterpret_cast<SelSmem*>(smem_raw);

    const int b   = blockIdx.x;
    const int tid = threadIdx.x;

    if (tid == 0) { S.sh_bin = 0u; S.sh_acc = 0u; S.ncand = 0u; }
    if (tid < 10) { S.validw[tid] = 0u; S.inw[tid] = 0u; }
    for (int i = tid; i < 4096; i += 1024) S.hist[i] = 0u;
    __syncthreads();

    {
        const unsigned* __restrict__ keys = g_keys + (size_t)b * NA;
        for (int i = tid; i < NA; i += 1024) {
            unsigned hi = keys[i];
            S.shi[i] = hi;
            unsigned d = hi >> 20;
            unsigned am = __activemask();
            unsigned mm = __match_any_sync(am, d);
            if ((tid & 31) == (int)(__ffs(mm) - 1u))
                atomicAdd(&S.hist[d], (unsigned)__popc(mm));
        }
    }
    __syncthreads();

    unsigned thresh24 = 0u;

#pragma unroll
    for (int pass = 0; pass < 2; ++pass) {
        if (tid < 512) {
            unsigned s = 0;
#pragma unroll
            for (int k = 0; k < 8; ++k) s += S.hist[tid * 8 + k];
            S.s8[tid] = s;
        }
        __syncthreads();
        if (tid < 32) {
            unsigned s = 0;
#pragma unroll
            for (int k = 0; k < 16; ++k) s += S.s8[tid * 16 + k];
#pragma unroll
            for (int off = 1; off < 32; off <<= 1) {
                unsigned v = __shfl_down_sync(0xffffffffu, s, off);
                if (tid + off < 32) s += v;
            }
            S.sgsuf[tid] = s;
            if (tid == 0) S.sgsuf[32] = 0u;
        }
        __syncthreads();
        unsigned need = (unsigned)MD - S.sh_acc;
        if (tid < 512) {
            int g = tid >> 4;
            unsigned ws = 0;
            for (int j = tid + 1; j < (g + 1) * 16; ++j) ws += S.s8[j];
            unsigned above = S.sgsuf[g + 1] + ws;
            unsigned here  = above + S.s8[tid];
            if (here >= need && above < need) {
                unsigned cum = above; int sel = 0;
#pragma unroll
                for (int k = 7; k >= 0; --k) {
                    unsigned c = S.hist[tid * 8 + k];
                    if (cum + c >= need) { sel = k; break; }
                    cum += c;
                }
                S.sh_bin = (unsigned)(tid * 8 + sel);
                S.sh_acc += cum;
            }
        }
        __syncthreads();

        if (pass == 0) {
            unsigned p0 = S.sh_bin;
            __syncthreads();
            for (int i = tid; i < 4096; i += 1024) S.hist[i] = 0u;
            __syncthreads();
            for (int i = tid; i < NA; i += 1024) {
                unsigned hi = S.shi[i];
                if ((hi >> 20) == p0) {
                    unsigned d = (hi >> 8) & 0xFFFu;
                    unsigned am = __activemask();
                    unsigned mm = __match_any_sync(am, d);
                    if ((tid & 31) == (int)(__ffs(mm) - 1u))
                        atomicAdd(&S.hist[d], (unsigned)__popc(mm));
                }
            }
            __syncthreads();
            thresh24 = p0 << 12;
        } else {
            thresh24 |= S.sh_bin;
        }
    }

    for (int i = tid; i < NA; i += 1024) {
        unsigned hi = S.shi[i];
        if ((hi >> 8) >= thresh24) {
            unsigned p = atomicAdd(&S.ncand, 1u);
            if (p < 512u)
                S.cand[p] = ((unsigned long long)hi << 32) | (unsigned)(~(unsigned)i);
        }
    }
    __syncthreads();
    {
        unsigned nc = S.ncand; if (nc > 512u) nc = 512u;
        if (tid < 512 && (unsigned)tid >= nc) S.cand[tid] = 0ull;
    }
    __syncthreads();

    unsigned long long v = (tid < 512) ? S.cand[tid] : 0ull;
    for (int size = 2; size <= 512; size <<= 1) {
        for (int stride = size >> 1; stride > 0; stride >>= 1) {
            if (stride >= 32) {
                __syncthreads();
                if (tid < 512) S.cand[tid] = v;
                __syncthreads();
                if (tid < 512) {
                    unsigned long long vp = S.cand[tid ^ stride];
                    bool takeMax = ((tid & stride) == 0) == ((tid & size) == 0);
                    v = takeMax ? (v > vp ? v : vp) : (v < vp ? v : vp);
                }
            } else if (tid < 512) {
                unsigned long long vp = __shfl_xor_sync(0xffffffffu, v, stride);
                bool takeMax = ((tid & stride) == 0) == ((tid & size) == 0);
                v = takeMax ? (v > vp ? v : vp) : (v < vp ? v : vp);
            }
        }
    }

    if (tid < MD) {
        unsigned long long kk = v;
        unsigned aidx = ~((unsigned)kk);
        bool valid = (kk >> 32) != 0ull;
        if (!valid) aidx = 0;
        const float* a = pred + (size_t)(b * NA + aidx) * ROWF;

        float x = a[0], y = a[1], w = a[2], h = a[3], obj = a[4];

        float conf = a[5]; int cls = 0;
#pragma unroll 8
        for (int k = 1; k < 80; ++k) {
            float c = a[5 + k];
            if (c > conf) { conf = c; cls = k; }       // first-max == jnp.argmax
        }

        float hw = __fmul_rn(w, 0.5f), hh = __fmul_rn(h, 0.5f);
        float4 v0 = make_float4(__fadd_rn(x,-hw), __fadd_rn(y,-hh),
                                __fadd_rn(x, hw), __fadd_rn(y, hh));

        g_sbox[b*MD + tid]  = v0;
        g_sarea[b*MD + tid] = __fmul_rn(fmaxf(__fadd_rn(v0.z, -v0.x), 0.f),
                                        fmaxf(__fadd_rn(v0.w, -v0.y), 0.f));
        if (valid) atomicOr(&S.validw[tid >> 5], 1u << (tid & 31));

        float cx = __fmul_rn(__fadd_rn(v0.x, v0.z), 0.5f);
        float cy = __fmul_rn(__fadd_rn(v0.y, v0.w), 0.5f);

        int cnt = 0;
#pragma unroll
        for (int k2 = 0; k2 < 8; ++k2) {
            int km = (k2 + 7) & 7;
            float xi = zone[2*k2], yi = zone[2*k2+1];
            float xj = zone[2*km], yj = zone[2*km+1];
            bool gyi = yi > cy, gyj = yj > cy;
            if (gyi != gyj) {
                float gx = __fadd_rn(
                    __fdiv_rn(__fmul_rn(__fadd_rn(xj,-xi), __fadd_rn(cy,-yi)),
                              __fadd_rn(yj,-yi)), xi);
                if (gx > cx) cnt++;
            }
        }
        if (cnt & 1) atomicOr(&S.inw[tid >> 5], 1u << (tid & 31));

        size_t o = (size_t)b * MD + tid;
        out[OF_BOX + o*4 + 0] = v0.y;  out[OF_BOX + o*4 + 1] = v0.x;
        out[OF_BOX + o*4 + 2] = v0.w;  out[OF_BOX + o*4 + 3] = v0.z;
        out[OF_SC  + o]       = fmaxf(obj, conf);
        out[OF_CLS + o]       = (float)cls;
        out[OF_CTR + o*2]     = cy;    out[OF_CTR + o*2 + 1] = cx;
    }
    __syncthreads();
    if (tid < 10) {
        g_flags[b*20 + tid]      = S.validw[tid];
        g_flags[b*20 + 10 + tid] = S.inw[tid];
    }
}

// ---------------------------------------------------------------------------
// Kernel C (R12 best): suppression bitmask (320 blocks x 640).
// ---------------------------------------------------------------------------
__global__ void __launch_bounds__(640) mask_kernel()
{
    __shared__ float4 sbb[MD];
    __shared__ float  sA[MD];

    const int b  = blockIdx.x / 10;
    const int rg = blockIdx.x % 10;
    const int tid = threadIdx.x;

    if (tid < MD) { sbb[tid] = g_sbox[b*MD + tid]; sA[tid] = g_sarea[b*MD + tid]; }
    __syncthreads();

    int w = tid >> 5, l = tid & 31;
    int c    = w % 10;
    int half = w / 10;
    int i0   = rg * 30 + half * 15;
    int j    = c * 32 + l;
    int jmax = c * 32 + 31;
    bool jv  = (j < MD);
    float4 bj = jv ? sbb[j] : make_float4(0,0,0,0);
    float  ja = jv ? sA[j] : 0.f;

    for (int i = i0; i < i0 + 15; ++i) {
        unsigned bits = 0u;
        if (jmax > i) {
            float4 bi = sbb[i];
            float  ia = sA[i];
            bool sup = false;
            if (jv && j > i) {
                float ltx = fmaxf(bi.x, bj.x), lty = fmaxf(bi.y, bj.y);
                float rbx = fminf(bi.z, bj.z), rby = fminf(bi.w, bj.w);
                float iw  = fmaxf(__fadd_rn(rbx, -ltx), 0.f);
                float ih  = fmaxf(__fadd_rn(rby, -lty), 0.f);
                float inter = __fmul_rn(iw, ih);
                float denom = __fadd_rn(__fadd_rn(__fadd_rn(ia, ja), -inter), 1e-9f);
                sup = inter > __fmul_rn(NMS_T, denom);
            }
            bits = __ballot_sync(0xffffffffu, sup);
        }
        if (l == 0) g_mask[(b*MD + i)*10 + c] = bits;
    }
}

// ---------------------------------------------------------------------------
// Kernel D (R14 best): block-closure scan; mask staged via ONE 12KB TMA copy.
// ---------------------------------------------------------------------------
__global__ void __launch_bounds__(512, 1) fin_kernel(float* __restrict__ out)
{
    __shared__ __align__(16) unsigned smask[320*10];   // rows 300..319 zero
    __shared__ __align__(8)  unsigned long long mbar;
    __shared__ unsigned keepw[10];
    __shared__ unsigned flg[20];

    const int b   = blockIdx.x;
    const int tid = threadIdx.x;
    const uint32_t mb = smem_u32(&mbar);

    if (tid == 0) mbar_init1(mb);
    __syncthreads();
    if (tid == 0) {
        mbar_expect(mb, (unsigned)(MD*10*4));
        tma_1d(smem_u32(smask), g_mask + (size_t)b*MD*10, (unsigned)(MD*10*4), mb);
    }
    for (int i = 3000 + tid; i < 3200; i += 512) smask[i] = 0u;  // overlaps TMA
    if (tid < 20) flg[tid] = g_flags[b*20 + tid];
    __syncthreads();
    mbar_wait0(mb);

    if (tid < 32) {
        const int l  = tid;
        const int lw = (l < 10) ? l : 0;
        unsigned kw = (l < 10) ? flg[l] : 0u;

        for (int blk = 0; blk < 10; ++blk) {
            unsigned alive = __shfl_sync(0xffffffffu, kw, blk);
            const int base = blk * 32;

            unsigned r[32];
#pragma unroll
            for (int k = 0; k < 32; ++k)
                r[k] = smask[(base + k)*10 + blk];     // broadcast LDS

#pragma unroll
            for (int k = 0; k < 32; ++k)
                alive &= ~(r[k] & (unsigned)(((int)(alive << (31 - k))) >> 31));

#pragma unroll
            for (int k = 0; k < 32; ++k) {
                unsigned am = (unsigned)(((int)(alive << (31 - k))) >> 31);
                kw &= ~(smask[(base + k)*10 + lw] & am);
            }
        }
        if (l < 10) keepw[l] = kw;
    }
    __syncthreads();

    if (tid < MD) {
        unsigned kp = (keepw[tid >> 5] >> (tid & 31)) & 1u;
        unsigned in = (flg[10 + (tid >> 5)] >> (tid & 31)) & 1u;
        size_t o = (size_t)b * MD + tid;
        out[OF_KEEP + o] = (float)kp;
        out[OF_INZ  + o] = (kp && in) ? 1.f : 0.f;
    }
}

extern "C" void kernel_launch(void* const* d_in, const int* in_sizes, int n_in,
                              void* d_out, int out_size)
{
    const float* pred = (const float*)d_in[0];
    const float* zone = (const float*)d_in[1];
    float* out = (float*)d_out;

    static int attr_done = 0;
    if (!attr_done) {
        cudaFuncSetAttribute(select_kernel,
                             cudaFuncAttributeMaxDynamicSharedMemorySize,
                             SEL_SMEM_BYTES);
        attr_done = 1;
    }

    score_kernel<<<TOTAL / 128, 256>>>(pred);
    select_kernel<<<NB, 1024, SEL_SMEM_BYTES>>>(pred, zone, out);
    mask_kernel<<<NB * 10, 640>>>();
    fin_kernel<<<NB, 512>>>(out);
}